// round 14
// baseline (speedup 1.0000x reference)
#include <cuda_runtime.h>
#include <cuda_bf16.h>
#include <string.h>

#define T_STEPS 8192
#define HID     1024
#define G4      4096   // 4*HID
#define INW     1024
#define NCTA    128

// ---------------- static device scratch (no runtime allocation) --------------
__device__ float g_pre[(size_t)T_STEPS * G4];    // 128 MB: x-projection of gates
__device__ float g_hall[(size_t)T_STEPS * HID];  // 32 MB: all hidden states
// tagged h ring: element = (tag:32 << 32) | float_bits(h).  slot = t&1, tag = t+1
__device__ __align__(32) unsigned long long g_htag[2][HID];

// ---------------- small PTX helpers ------------------------------------------
__device__ __forceinline__ ulonglong2 ld_tag_v2(const unsigned long long* p) {
    ulonglong2 v;
    asm volatile("ld.relaxed.gpu.global.v2.u64 {%0,%1}, [%2];"
                 : "=l"(v.x), "=l"(v.y) : "l"(p) : "memory");
    return v;
}
__device__ __forceinline__ void st_tag_u64(unsigned long long* p, unsigned long long v) {
    asm volatile("st.relaxed.gpu.global.u64 [%0], %1;" :: "l"(p), "l"(v) : "memory");
}
__device__ __forceinline__ float2 ffma2(float2 a, float2 b, float2 c) {
    unsigned long long A, B, C, D;
    memcpy(&A, &a, 8); memcpy(&B, &b, 8); memcpy(&C, &c, 8);
    asm("fma.rn.f32x2 %0, %1, %2, %3;" : "=l"(D) : "l"(A), "l"(B), "l"(C));
    float2 d; memcpy(&d, &D, 8); return d;
}
__device__ __forceinline__ float2 fpack2(float a) {
    float2 r;
    unsigned long long R;
    asm("mov.b64 %0, {%1, %1};" : "=l"(R) : "f"(a));
    memcpy(&r, &R, 8); return r;
}
__device__ __forceinline__ float fsig(float x) {
    return __fdividef(1.0f, 1.0f + __expf(-x));
}
__device__ __forceinline__ float ftanh_acc(float x) {
    float xc = fminf(fmaxf(x, -15.0f), 15.0f);
    float e  = __expf(2.0f * xc);
    return __fdividef(e - 1.0f, e + 1.0f);
}

// ---------------- init: zero the tagged ring ----------------------------------
__global__ void init_tags_kernel() {
    int i = blockIdx.x * blockDim.x + threadIdx.x;
    if (i < 2 * HID) ((unsigned long long*)g_htag)[i] = 0ull;
}

// ---------------- fp32 NT GEMM: C = A*B^T + bias (reg-staged pipeline) --------
__device__ __forceinline__ void gemm_body(
    const float* __restrict__ A, int lda,
    const float* __restrict__ B, int ldb,
    const float* __restrict__ bias,
    float* __restrict__ C, int ldc, int K)
{
    __shared__ float As[16][132];
    __shared__ float Bs[16][132];

    const int tid  = threadIdx.x;
    const int tx   = tid & 15;
    const int ty   = tid >> 4;
    const int brow = blockIdx.y * 128;
    const int bcol = blockIdx.x * 128;
    const int lr   = tid >> 2;
    const int lc   = (tid & 3) << 2;

    float2 acc[8][4];
#pragma unroll
    for (int i = 0; i < 8; i++)
#pragma unroll
        for (int j = 0; j < 4; j++) acc[i][j] = make_float2(0.0f, 0.0f);

    const float* Aptr = A + (size_t)(brow + lr) * lda + lc;
    const float* Bptr = B + (size_t)(bcol + lr) * ldb + lc;

    float4 va[2], vb[2];
#pragma unroll
    for (int r = 0; r < 2; r++) {
        va[r] = *(const float4*)(Aptr + (size_t)(64 * r) * lda);
        vb[r] = *(const float4*)(Bptr + (size_t)(64 * r) * ldb);
    }

    const int NT = K / 16;
    for (int tile = 0; tile < NT; ++tile) {
#pragma unroll
        for (int r = 0; r < 2; r++) {
            As[lc + 0][lr + 64 * r] = va[r].x;
            As[lc + 1][lr + 64 * r] = va[r].y;
            As[lc + 2][lr + 64 * r] = va[r].z;
            As[lc + 3][lr + 64 * r] = va[r].w;
            Bs[lc + 0][lr + 64 * r] = vb[r].x;
            Bs[lc + 1][lr + 64 * r] = vb[r].y;
            Bs[lc + 2][lr + 64 * r] = vb[r].z;
            Bs[lc + 3][lr + 64 * r] = vb[r].w;
        }
        __syncthreads();

        if (tile + 1 < NT) {
            const int k0 = (tile + 1) * 16;
#pragma unroll
            for (int r = 0; r < 2; r++) {
                va[r] = *(const float4*)(Aptr + (size_t)(64 * r) * lda + k0);
                vb[r] = *(const float4*)(Bptr + (size_t)(64 * r) * ldb + k0);
            }
        }

#pragma unroll
        for (int kk = 0; kk < 16; kk++) {
            float  ra[8];
            float2 rb[4];
            *(float4*)(ra)     = *(const float4*)&As[kk][ty * 8];
            *(float4*)(ra + 4) = *(const float4*)&As[kk][ty * 8 + 4];
            *(float4*)(&rb[0]) = *(const float4*)&Bs[kk][tx * 8];
            *(float4*)(&rb[2]) = *(const float4*)&Bs[kk][tx * 8 + 4];
#pragma unroll
            for (int i = 0; i < 8; i++) {
                float2 a2 = fpack2(ra[i]);
#pragma unroll
                for (int j = 0; j < 4; j++)
                    acc[i][j] = ffma2(a2, rb[j], acc[i][j]);
            }
        }
        __syncthreads();
    }

    float2 bv[4];
    *(float4*)(&bv[0]) = *(const float4*)&bias[bcol + tx * 8];
    *(float4*)(&bv[2]) = *(const float4*)&bias[bcol + tx * 8 + 4];
#pragma unroll
    for (int i = 0; i < 8; i++) {
        float4 o0, o1;
        o0.x = acc[i][0].x + bv[0].x; o0.y = acc[i][0].y + bv[0].y;
        o0.z = acc[i][1].x + bv[1].x; o0.w = acc[i][1].y + bv[1].y;
        o1.x = acc[i][2].x + bv[2].x; o1.y = acc[i][2].y + bv[2].y;
        o1.z = acc[i][3].x + bv[3].x; o1.w = acc[i][3].y + bv[3].y;
        float* crow = C + (size_t)(brow + ty * 8 + i) * ldc + bcol + tx * 8;
        *(float4*)(crow)     = o0;
        *(float4*)(crow + 4) = o1;
    }
}

__global__ void __launch_bounds__(256, 2) gemm_pre_kernel(
    const float* __restrict__ x, const float* __restrict__ Ww,
    const float* __restrict__ Wb)
{
    gemm_body(x, INW, Ww, INW + HID, Wb, g_pre, G4, INW);
}

__global__ void __launch_bounds__(256, 2) gemm_out_kernel(
    const float* __restrict__ ow, const float* __restrict__ ob,
    float* __restrict__ out)
{
    gemm_body(g_hall, HID, ow, HID, ob, out, HID, HID);
}

// ---------------- persistent LSTM recurrence (frozen skeleton, k-split dot) ---
// 128 CTAs x 512 threads (16 warps). CTA owns units [8b, 8b+8).
// NEW warp mapping: warp w computes gate (w>>2) for ALL 8 units over k-range
// (w&3)*256 .. +255.  Each warp reads only 1KB of h -> CTA smem crossbar
// traffic 16KB/step (was 64KB).  Weights: 64 floats/thread in regs (as before,
// transposed layout).  Reduce: 3-stage butterfly value-exchange (9 SHFL) gives
// lane l the full sum for unit rev3(l&7); lanes 0..7 publish to gqk.
// Cell update / tagged store / per-thread poll / 2 barriers: IDENTICAL to R12.
__global__ void __launch_bounds__(512, 1) lstm_kernel(
    const float* __restrict__ Ww)
{
    const int tid  = threadIdx.x;
    const int w    = tid >> 5;
    const int lane = tid & 31;
    const int gate = w >> 2;          // 0=i, 1=f, 2=g, 3=o
    const int kg   = w & 3;           // k-group
    const int u0   = blockIdx.x * 8;
    const int kbase = kg * 256 + lane * 8;   // this thread's 8 k-values

    __shared__ float sh[HID];          // h_{t-1} stage
    __shared__ float gqk[8][4][4];     // [unit][gate][kgroup] partial sums

    // ---- weights: gate row (gate*1024 + u0 + u), cols INW+kbase..+7, u=0..7 --
    float4 wreg[8][2];
#pragma unroll
    for (int u = 0; u < 8; u++) {
        const float* row = Ww + (size_t)(gate * 1024 + u0 + u) * (INW + HID) + INW + kbase;
        wreg[u][0] = *(const float4*)(row);
        wreg[u][1] = *(const float4*)(row + 4);
    }

    // h_{-1} = 0
    ((float2*)sh)[tid] = make_float2(0.0f, 0.0f);

    // cell threads (tid<8) prefetch pre[0] for their unit's 4 gates
    float pr[4] = {0.f, 0.f, 0.f, 0.f};
    if (tid < 8) {
#pragma unroll
        for (int g = 0; g < 4; g++)
            pr[g] = g_pre[(size_t)g * 1024 + u0 + tid];
    }

    float c_state = 0.0f;   // live only in threads 0..7
    __syncthreads();

    for (int t = 0; t < T_STEPS; t++) {
        // ---- k-split dot: 8 units x 8 k per thread ----
        float4 h4a = *(const float4*)&sh[kbase];
        float4 h4b = *(const float4*)&sh[kbase + 4];
        float2 h01 = make_float2(h4a.x, h4a.y);
        float2 h23 = make_float2(h4a.z, h4a.w);
        float2 h45 = make_float2(h4b.x, h4b.y);
        float2 h67 = make_float2(h4b.z, h4b.w);

        float s[8];
#pragma unroll
        for (int u = 0; u < 8; u++) {
            float2 acc = make_float2(0.0f, 0.0f);
            acc = ffma2(make_float2(wreg[u][0].x, wreg[u][0].y), h01, acc);
            acc = ffma2(make_float2(wreg[u][0].z, wreg[u][0].w), h23, acc);
            acc = ffma2(make_float2(wreg[u][1].x, wreg[u][1].y), h45, acc);
            acc = ffma2(make_float2(wreg[u][1].z, wreg[u][1].w), h67, acc);
            s[u] = acc.x + acc.y;
        }

        // ---- butterfly multi-reduce: 3 value-exchange stages + 2 plain ----
#pragma unroll
        for (int st = 0; st < 3; st++) {
            const int off = 1 << st;
            const int nv  = 4 >> st;       // 4, 2, 1
            const bool hi = (lane >> st) & 1;
#pragma unroll
            for (int j = 0; j < nv; j++) {
                float send = hi ? s[j] : s[j + nv];
                float keep = hi ? s[j + nv] : s[j];
                float recv = __shfl_xor_sync(0xffffffffu, send, off);
                s[j] = keep + recv;
            }
        }
        s[0] += __shfl_xor_sync(0xffffffffu, s[0], 8);
        s[0] += __shfl_xor_sync(0xffffffffu, s[0], 16);
        // lane l now holds full sum for unit rev3(l&7)

        if (lane < 8) {
            int u = ((lane & 1) << 2) | (lane & 2) | ((lane >> 2) & 1);  // rev3
            gqk[u][gate][kg] = s[0];
        }
        __syncthreads();                               // barrier #1

        // ---- cell update (8 threads) + tagged store ----
        if (tid < 8) {
            float4 qi = *(const float4*)gqk[tid][0];
            float4 qf = *(const float4*)gqk[tid][1];
            float4 qg = *(const float4*)gqk[tid][2];
            float4 qo = *(const float4*)gqk[tid][3];
            float vi = (qi.x + qi.y) + (qi.z + qi.w) + pr[0];
            float vf = (qf.x + qf.y) + (qf.z + qf.w) + pr[1];
            float vg = (qg.x + qg.y) + (qg.z + qg.w) + pr[2];
            float vo = (qo.x + qo.y) + (qo.z + qo.w) + pr[3];
            float ig = fsig(vi);
            float fg = fsig(vf);
            float gg = ftanh_acc(vg);
            float og = fsig(vo);
            c_state = fg * c_state + ig * gg;
            float h = og * ftanh_acc(c_state);
            int uu = u0 + tid;
            unsigned long long word =
                ((unsigned long long)(t + 1) << 32) |
                (unsigned long long)__float_as_uint(h);
            st_tag_u64(&g_htag[t & 1][uu], word);
            g_hall[(size_t)t * HID + uu] = h;
        }

        if (t + 1 < T_STEPS) {
            // prefetch pre[t+1] (cell threads; overlaps the poll)
            if (tid < 8) {
#pragma unroll
                for (int g = 0; g < 4; g++)
                    pr[g] = g_pre[(size_t)(t + 1) * G4 + g * 1024 + u0 + tid];
            }

            // ---- per-thread poll: own 2 tagged words (R4-proven) ----
            const unsigned long long* src = &g_htag[t & 1][2 * tid];
            const unsigned long long want = (unsigned long long)(t + 1);
            ulonglong2 v;
            for (;;) {
                v = ld_tag_v2(src);
                if ((v.x >> 32) == want && (v.y >> 32) == want) break;
            }
            ((float2*)sh)[tid] = make_float2(
                __uint_as_float((unsigned)(v.x & 0xffffffffu)),
                __uint_as_float((unsigned)(v.y & 0xffffffffu)));
            __syncthreads();                           // barrier #2
        }
    }
}

// ---------------- launch -------------------------------------------------------
extern "C" void kernel_launch(void* const* d_in, const int* in_sizes, int n_in,
                              void* d_out, int out_size)
{
    const float* x   = (const float*)d_in[0];  // [8192, 1, 1024]
    const float* Ww  = (const float*)d_in[1];  // [4096, 2048]
    const float* Wb  = (const float*)d_in[2];  // [4096]
    const float* ow  = (const float*)d_in[3];  // [1024, 1024]
    const float* ob  = (const float*)d_in[4];  // [1024]
    float*       out = (float*)d_out;          // [8192, 1, 1024]

    init_tags_kernel<<<(2 * HID + 255) / 256, 256>>>();

    dim3 gridA(G4 / 128, T_STEPS / 128);       // 32 x 64
    gemm_pre_kernel<<<gridA, 256>>>(x, Ww, Wb);

    lstm_kernel<<<NCTA, 512>>>(Ww);

    dim3 gridC(HID / 128, T_STEPS / 128);      // 8 x 64
    gemm_out_kernel<<<gridC, 256>>>(ow, ob, out);
}

// round 15
// speedup vs baseline: 1.1510x; 1.1510x over previous
#include <cuda_runtime.h>
#include <cuda_bf16.h>
#include <string.h>
#include <cooperative_groups.h>
#include <cooperative_groups/reduce.h>

namespace cg = cooperative_groups;

#define T_STEPS 8192
#define HID     1024
#define G4      4096   // 4*HID
#define INW     1024
#define NCTA    128

// ---------------- static device scratch (no runtime allocation) --------------
__device__ float g_pre[(size_t)T_STEPS * G4];    // 128 MB: x-projection of gates
__device__ float g_hall[(size_t)T_STEPS * HID];  // 32 MB: all hidden states
// tagged h ring: element = (tag:32 << 32) | float_bits(h).  slot = t&1, tag = t+1
__device__ __align__(32) unsigned long long g_htag[2][HID];

// ---------------- small PTX helpers ------------------------------------------
__device__ __forceinline__ ulonglong2 ld_tag_v2(const unsigned long long* p) {
    ulonglong2 v;
    asm volatile("ld.relaxed.gpu.global.v2.u64 {%0,%1}, [%2];"
                 : "=l"(v.x), "=l"(v.y) : "l"(p) : "memory");
    return v;
}
__device__ __forceinline__ void st_tag_u64(unsigned long long* p, unsigned long long v) {
    asm volatile("st.relaxed.gpu.global.u64 [%0], %1;" :: "l"(p), "l"(v) : "memory");
}
__device__ __forceinline__ float2 ffma2(float2 a, float2 b, float2 c) {
    unsigned long long A, B, C, D;
    memcpy(&A, &a, 8); memcpy(&B, &b, 8); memcpy(&C, &c, 8);
    asm("fma.rn.f32x2 %0, %1, %2, %3;" : "=l"(D) : "l"(A), "l"(B), "l"(C));
    float2 d; memcpy(&d, &D, 8); return d;
}
__device__ __forceinline__ float2 fpack2(float a) {
    float2 r;
    unsigned long long R;
    asm("mov.b64 %0, {%1, %1};" : "=l"(R) : "f"(a));
    memcpy(&r, &R, 8); return r;
}
__device__ __forceinline__ float fsig(float x) {
    return __fdividef(1.0f, 1.0f + __expf(-x));
}
__device__ __forceinline__ float ftanh_acc(float x) {
    float xc = fminf(fmaxf(x, -15.0f), 15.0f);
    float e  = __expf(2.0f * xc);
    return __fdividef(e - 1.0f, e + 1.0f);
}

// ---------------- init: zero the tagged ring ----------------------------------
__global__ void init_tags_kernel() {
    int i = blockIdx.x * blockDim.x + threadIdx.x;
    if (i < 2 * HID) ((unsigned long long*)g_htag)[i] = 0ull;
}

// ---------------- fp32 NT GEMM: C = A*B^T + bias (reg-staged pipeline) --------
// A: [M x K] row-major (lda), B: [N x K] row-major (ldb), C: [M x N] (ldc)
// BM=BN=128, BK=16, 256 threads, 8x8 microtile (as 8x4 float2).
// CHANGE vs R12: warp-internal (tx,ty) remap — warp spans 8 tx x 4 ty instead
// of 16 tx x 2 ty -> smem read wavefronts per kk per warp drop 5 -> 3
// (B: 4->2, A: 1).  ncu showed L1 = 80% busy: this is the binding resource.
__device__ __forceinline__ void gemm_body(
    const float* __restrict__ A, int lda,
    const float* __restrict__ B, int ldb,
    const float* __restrict__ bias,
    float* __restrict__ C, int ldc, int K)
{
    __shared__ float As[16][132];
    __shared__ float Bs[16][132];

    const int tid  = threadIdx.x;
    const int tx   = (tid & 7) | ((tid & 128) >> 4);   // 8 distinct per warp
    const int ty   = (tid >> 3) & 15;                  // 4 distinct per warp
    const int brow = blockIdx.y * 128;
    const int bcol = blockIdx.x * 128;
    const int lr   = tid >> 2;
    const int lc   = (tid & 3) << 2;

    float2 acc[8][4];
#pragma unroll
    for (int i = 0; i < 8; i++)
#pragma unroll
        for (int j = 0; j < 4; j++) acc[i][j] = make_float2(0.0f, 0.0f);

    const float* Aptr = A + (size_t)(brow + lr) * lda + lc;
    const float* Bptr = B + (size_t)(bcol + lr) * ldb + lc;

    float4 va[2], vb[2];
#pragma unroll
    for (int r = 0; r < 2; r++) {
        va[r] = *(const float4*)(Aptr + (size_t)(64 * r) * lda);
        vb[r] = *(const float4*)(Bptr + (size_t)(64 * r) * ldb);
    }

    const int NT = K / 16;
    for (int tile = 0; tile < NT; ++tile) {
#pragma unroll
        for (int r = 0; r < 2; r++) {
            As[lc + 0][lr + 64 * r] = va[r].x;
            As[lc + 1][lr + 64 * r] = va[r].y;
            As[lc + 2][lr + 64 * r] = va[r].z;
            As[lc + 3][lr + 64 * r] = va[r].w;
            Bs[lc + 0][lr + 64 * r] = vb[r].x;
            Bs[lc + 1][lr + 64 * r] = vb[r].y;
            Bs[lc + 2][lr + 64 * r] = vb[r].z;
            Bs[lc + 3][lr + 64 * r] = vb[r].w;
        }
        __syncthreads();

        if (tile + 1 < NT) {
            const int k0 = (tile + 1) * 16;
#pragma unroll
            for (int r = 0; r < 2; r++) {
                va[r] = *(const float4*)(Aptr + (size_t)(64 * r) * lda + k0);
                vb[r] = *(const float4*)(Bptr + (size_t)(64 * r) * ldb + k0);
            }
        }

#pragma unroll
        for (int kk = 0; kk < 16; kk++) {
            float  ra[8];
            float2 rb[4];
            *(float4*)(ra)     = *(const float4*)&As[kk][ty * 8];
            *(float4*)(ra + 4) = *(const float4*)&As[kk][ty * 8 + 4];
            *(float4*)(&rb[0]) = *(const float4*)&Bs[kk][tx * 8];
            *(float4*)(&rb[2]) = *(const float4*)&Bs[kk][tx * 8 + 4];
#pragma unroll
            for (int i = 0; i < 8; i++) {
                float2 a2 = fpack2(ra[i]);
#pragma unroll
                for (int j = 0; j < 4; j++)
                    acc[i][j] = ffma2(a2, rb[j], acc[i][j]);
            }
        }
        __syncthreads();
    }

    float2 bv[4];
    *(float4*)(&bv[0]) = *(const float4*)&bias[bcol + tx * 8];
    *(float4*)(&bv[2]) = *(const float4*)&bias[bcol + tx * 8 + 4];
#pragma unroll
    for (int i = 0; i < 8; i++) {
        float4 o0, o1;
        o0.x = acc[i][0].x + bv[0].x; o0.y = acc[i][0].y + bv[0].y;
        o0.z = acc[i][1].x + bv[1].x; o0.w = acc[i][1].y + bv[1].y;
        o1.x = acc[i][2].x + bv[2].x; o1.y = acc[i][2].y + bv[2].y;
        o1.z = acc[i][3].x + bv[3].x; o1.w = acc[i][3].y + bv[3].y;
        float* crow = C + (size_t)(brow + ty * 8 + i) * ldc + bcol + tx * 8;
        *(float4*)(crow)     = o0;
        *(float4*)(crow + 4) = o1;
    }
}

__global__ void __launch_bounds__(256, 2) gemm_pre_kernel(
    const float* __restrict__ x, const float* __restrict__ Ww,
    const float* __restrict__ Wb)
{
    gemm_body(x, INW, Ww, INW + HID, Wb, g_pre, G4, INW);
}

__global__ void __launch_bounds__(256, 2) gemm_out_kernel(
    const float* __restrict__ ow, const float* __restrict__ ob,
    float* __restrict__ out)
{
    gemm_body(g_hall, HID, ow, HID, ob, out, HID, HID);
}

// ---------------- persistent LSTM recurrence (R12, FROZEN) --------------------
// 128 CTAs x 512 threads (16 warps). CTA owns units [8b, 8b+8).
// Warp w (w<8):  rows rA=u0+w (i-gate), rB=rA+1024 (f-gate)
// Warp w (w>=8): rows rA=u0+(w-8)+2048 (g-gate), rB=rA+1024 (o-gate)
// Exchange: per-thread fused tag+data poll of own 2 words.
// Reduce: cg::reduce -> REDUX.SUM.F32.  Two full barriers per step.
__global__ void __launch_bounds__(512, 1) lstm_kernel(const float* __restrict__ Ww)
{
    const int tid  = threadIdx.x;
    const int w    = tid >> 5;
    const int lane = tid & 31;
    const int d    = w & 7;
    const int u    = blockIdx.x * 8 + d;
    const int rA   = (w < 8) ? u : (u + 2048);
    const int rB   = rA + 1024;

    auto warp32 = cg::tiled_partition<32>(cg::this_thread_block());

    __shared__ float  sh[HID];   // h_{t-1} stage (single buffer: reads complete
                                 // before barrier #1; poll writes after it)
    __shared__ float4 gq[8];     // (i, f, g, o) per unit

    // recurrent weights (columns 1024..2047 of Ww) in registers
    float2 wa[16], wb[16];
    {
        const float2* WA = (const float2*)(Ww + (size_t)rA * (INW + HID) + INW);
        const float2* WB = (const float2*)(Ww + (size_t)rB * (INW + HID) + INW);
#pragma unroll
        for (int i = 0; i < 16; i++) {
            wa[i] = WA[lane + 32 * i];
            wb[i] = WB[lane + 32 * i];
        }
    }

    // h_{-1} = 0
    ((float2*)sh)[tid] = make_float2(0.0f, 0.0f);

    // pre[0] for this warp's 2 rows (lane 0 only)
    float preA = 0.0f, preB = 0.0f;
    if (lane == 0) {
        preA = g_pre[rA];
        preB = g_pre[rB];
    }

    float c_state = 0.0f;   // live only in threads 0..7
    __syncthreads();

    for (int t = 0; t < T_STEPS; t++) {
        // ---- dot products over h_{t-1} in sh ----
        float2 aA = make_float2(0.0f, 0.0f);
        float2 aB = make_float2(0.0f, 0.0f);
        const float2* hp = (const float2*)sh;
#pragma unroll
        for (int i = 0; i < 16; i++) {
            float2 h2 = hp[lane + 32 * i];
            aA = ffma2(wa[i], h2, aA);
            aB = ffma2(wb[i], h2, aB);
        }
        // warp reduce: REDUX.SUM.F32 on sm_103a via cooperative_groups
        float sA = cg::reduce(warp32, aA.x + aA.y, cg::plus<float>());
        float sB = cg::reduce(warp32, aB.x + aB.y, cg::plus<float>());

        if (lane == 0) {
            if (w < 8) { gq[d].x = sA + preA; gq[d].y = sB + preB; }
            else       { gq[d].z = sA + preA; gq[d].w = sB + preB; }
        }
        __syncthreads();                               // barrier #1

        // ---- cell update (8 threads, all in warp 0) + tagged store ----
        if (tid < 8) {
            float4 G = gq[tid];
            float ig = fsig(G.x);
            float fg = fsig(G.y);
            float gg = ftanh_acc(G.z);
            float og = fsig(G.w);
            c_state = fg * c_state + ig * gg;
            float h = og * ftanh_acc(c_state);
            int uu = blockIdx.x * 8 + tid;
            unsigned long long word =
                ((unsigned long long)(t + 1) << 32) |
                (unsigned long long)__float_as_uint(h);
            st_tag_u64(&g_htag[t & 1][uu], word);
            g_hall[(size_t)t * HID + uu] = h;
        }

        if (t + 1 < T_STEPS) {
            // prefetch pre[t+1] (overlaps the poll)
            if (lane == 0) {
                preA = g_pre[(size_t)(t + 1) * G4 + rA];
                preB = g_pre[(size_t)(t + 1) * G4 + rB];
            }

            // ---- per-thread poll: own 2 tagged words (R4-proven) ----
            const unsigned long long* src = &g_htag[t & 1][2 * tid];
            const unsigned long long want = (unsigned long long)(t + 1);
            ulonglong2 v;
            for (;;) {
                v = ld_tag_v2(src);
                if ((v.x >> 32) == want && (v.y >> 32) == want) break;
            }
            ((float2*)sh)[tid] = make_float2(
                __uint_as_float((unsigned)(v.x & 0xffffffffu)),
                __uint_as_float((unsigned)(v.y & 0xffffffffu)));
            __syncthreads();                           // barrier #2
        }
    }
}

// ---------------- launch -------------------------------------------------------
extern "C" void kernel_launch(void* const* d_in, const int* in_sizes, int n_in,
                              void* d_out, int out_size)
{
    const float* x   = (const float*)d_in[0];  // [8192, 1, 1024]
    const float* Ww  = (const float*)d_in[1];  // [4096, 2048]
    const float* Wb  = (const float*)d_in[2];  // [4096]
    const float* ow  = (const float*)d_in[3];  // [1024, 1024]
    const float* ob  = (const float*)d_in[4];  // [1024]
    float*       out = (float*)d_out;          // [8192, 1, 1024]

    init_tags_kernel<<<(2 * HID + 255) / 256, 256>>>();

    dim3 gridA(G4 / 128, T_STEPS / 128);       // 32 x 64
    gemm_pre_kernel<<<gridA, 256>>>(x, Ww, Wb);

    lstm_kernel<<<NCTA, 512>>>(Ww);

    dim3 gridC(HID / 128, T_STEPS / 128);      // 8 x 64
    gemm_out_kernel<<<gridC, 256>>>(ow, ob, out);
}